// round 2
// baseline (speedup 1.0000x reference)
#include <cuda_runtime.h>
#include <math.h>

#define B 8
#define NPIX 4096
#define C 512
#define HEADS 16
#define HD 32

// ---------------- scratch (device globals; no runtime allocation) ----------
__device__ float g_qn[B*C*NPIX];        // q projection, (b,c,n) layout
__device__ float g_kn[B*C*NPIX];        // k projection, (b,c,n) layout
__device__ float g_gate[2*B*NPIX];      // spatial gate logits -> sigmoid (q then k)
__device__ float g_pool[2*B*C];
__device__ float g_cs[2*B*C];           // channel gate (q then k)
__device__ float g_cosT[256*NPIX];      // rope cos, (j, n) layout
__device__ float g_sinT[256*NPIX];
__device__ float g_kv[B*HEADS*HD*HD];
__device__ float g_km[B*HEADS*HD];

__device__ __forceinline__ float acc_sigmoid(float x) {
    return 1.0f / (1.0f + expf(-x));
}
__device__ __forceinline__ float elu1(float x) {
    return x > 0.0f ? x + 1.0f : expf(x);
}

// ---------------- rope repack: (n,256) -> (256,n) ---------------------------
__global__ void repack_rope(const float* __restrict__ rc, const float* __restrict__ rs) {
    int idx = blockIdx.x * blockDim.x + threadIdx.x;   // 256*4096 total
    int j = idx >> 12;
    int n = idx & 4095;
    g_cosT[idx] = rc[n*256 + j];
    g_sinT[idx] = rs[n*256 + j];
}

__global__ void zero_gate() {
    int i = blockIdx.x * blockDim.x + threadIdx.x;
    if (i < 2*B*NPIX) g_gate[i] = 0.f;
}

// ---------------- GEMM: qk = x @ qk_w^T + b, transposed store --------------
// M=32768, N=1024, K=512. BM=128, BN=64, BK=16, 256 thr, 8x4 micro-tile.
__global__ __launch_bounds__(256) void gemm_qk(const float* __restrict__ x,
                                               const float* __restrict__ w,
                                               const float* __restrict__ bias) {
    __shared__ __align__(16) float As[16][136];
    __shared__ __align__(16) float Bs[16][72];
    __shared__ __align__(16) float stage[128][17];

    int tid = threadIdx.x;
    int m0 = blockIdx.y * 128;
    int o0 = blockIdx.x * 64;
    int tr = tid >> 4;   // 0..15 over m (8 rows each)
    int tc = tid & 15;   // 0..15 over o (4 cols each)

    float acc[8][4];
    #pragma unroll
    for (int i = 0; i < 8; i++)
        #pragma unroll
        for (int j = 0; j < 4; j++) acc[i][j] = 0.f;

    for (int k0 = 0; k0 < 512; k0 += 16) {
        #pragma unroll
        for (int i = 0; i < 2; i++) {
            int lin = tid + 256*i;
            int ml = lin >> 2;
            int kl = (lin & 3) << 2;
            float4 v = *(const float4*)(x + (size_t)(m0+ml)*512 + k0 + kl);
            As[kl+0][ml] = v.x; As[kl+1][ml] = v.y;
            As[kl+2][ml] = v.z; As[kl+3][ml] = v.w;
        }
        {
            int ol = tid >> 2;
            int kl = (tid & 3) << 2;
            float4 v = *(const float4*)(w + (size_t)(o0+ol)*512 + k0 + kl);
            Bs[kl+0][ol] = v.x; Bs[kl+1][ol] = v.y;
            Bs[kl+2][ol] = v.z; Bs[kl+3][ol] = v.w;
        }
        __syncthreads();
        #pragma unroll
        for (int kk = 0; kk < 16; kk++) {
            float a[8], bb[4];
            float4 a0 = *(const float4*)&As[kk][tr*8];
            float4 a1 = *(const float4*)&As[kk][tr*8 + 4];
            a[0]=a0.x; a[1]=a0.y; a[2]=a0.z; a[3]=a0.w;
            a[4]=a1.x; a[5]=a1.y; a[6]=a1.z; a[7]=a1.w;
            float4 b0 = *(const float4*)&Bs[kk][tc*4];
            bb[0]=b0.x; bb[1]=b0.y; bb[2]=b0.z; bb[3]=b0.w;
            #pragma unroll
            for (int i = 0; i < 8; i++)
                #pragma unroll
                for (int j = 0; j < 4; j++)
                    acc[i][j] = fmaf(a[i], bb[j], acc[i][j]);
        }
        __syncthreads();
    }

    float bv[4];
    #pragma unroll
    for (int j = 0; j < 4; j++) bv[j] = bias[o0 + tc*4 + j];

    int mychunk = tc >> 2;          // which 16-o chunk this thread's cols are in
    for (int ch = 0; ch < 4; ch++) {
        __syncthreads();
        if (mychunk == ch) {
            int obase = (tc & 3) * 4;
            #pragma unroll
            for (int i = 0; i < 8; i++)
                #pragma unroll
                for (int j = 0; j < 4; j++)
                    stage[tr*8 + i][obase + j] = acc[i][j] + bv[j];
        }
        __syncthreads();
        #pragma unroll
        for (int ii = 0; ii < 8; ii++) {
            int lin = tid + 256*ii;
            int ml = lin & 127;
            int ol = lin >> 7;
            int o = o0 + ch*16 + ol;
            int m = m0 + ml;
            int bb2 = m >> 12;
            int n = m & 4095;
            float val = stage[ml][ol];
            if (o < 512) g_qn[((size_t)(bb2*C + o))*NPIX + n] = val;
            else         g_kn[((size_t)(bb2*C + (o-512)))*NPIX + n] = val;
        }
    }
}

// ---------------- spatial gate: dwconv+BN+relu, reduce over channels -------
// block: 4 rows x 64 cols of one image, 64-channel chunk; atomicAdd partials.
__global__ __launch_bounds__(256) void gate_accum(int which,
        const float* __restrict__ dww, const float* __restrict__ dwb,
        const float* __restrict__ bng, const float* __restrict__ bnb,
        const float* __restrict__ pww) {
    const float* src = which ? g_kn : g_qn;
    float* slog = g_gate + which * B * NPIX;
    int b  = blockIdx.z;
    int r0 = blockIdx.x * 4;
    int c0 = blockIdx.y * 64;
    int tid = threadIdx.x;
    int r  = tid >> 6;
    int wx = tid & 63;
    __shared__ float tile[6][64];
    const float invs = 1.0f / sqrtf(1.0f + 1e-5f);
    float acc = 0.f;
    for (int c = c0; c < c0 + 64; c++) {
        const float* plane = src + ((size_t)(b*C + c)) * NPIX;
        for (int lin = tid; lin < 384; lin += 256) {
            int rr = (lin >> 6) + r0 - 1;
            int cc = lin & 63;
            tile[lin >> 6][cc] = (rr >= 0 && rr < 64) ? plane[rr*64 + cc] : 0.f;
        }
        __syncthreads();
        float conv = 0.f;
        #pragma unroll
        for (int kh = 0; kh < 3; kh++) {
            #pragma unroll
            for (int kw = 0; kw < 3; kw++) {
                int cc = wx + kw - 1;
                float v = (cc >= 0 && cc < 64) ? tile[r + kh][cc] : 0.f;
                conv = fmaf(v, dww[c*9 + kh*3 + kw], conv);
            }
        }
        float y = (conv + dwb[c]) * (bng[c] * invs) + bnb[c];
        y = fmaxf(y, 0.f);
        acc = fmaf(y, pww[c], acc);
        __syncthreads();
    }
    atomicAdd(&slog[b*NPIX + (r0 + r)*64 + wx], acc);
}

__global__ void gate_sigmoid() {
    int i = blockIdx.x * blockDim.x + threadIdx.x;
    if (i < 2*B*NPIX) g_gate[i] = acc_sigmoid(g_gate[i]);
}

// ---------------- channel pool + SE gemm -----------------------------------
__global__ __launch_bounds__(256) void pool_kernel() {
    int t = blockIdx.z, b = blockIdx.y, c = blockIdx.x;
    const float* src  = t ? g_kn : g_qn;
    const float* gate = g_gate + t*B*NPIX + b*NPIX;
    const float* plane = src + ((size_t)(b*C + c)) * NPIX;
    float s = 0.f;
    for (int n = threadIdx.x; n < NPIX; n += 256) s = fmaf(plane[n], gate[n], s);
    __shared__ float red[8];
    for (int off = 16; off; off >>= 1) s += __shfl_down_sync(0xffffffffu, s, off);
    if ((threadIdx.x & 31) == 0) red[threadIdx.x >> 5] = s;
    __syncthreads();
    if (threadIdx.x < 8) {
        s = red[threadIdx.x];
        for (int off = 4; off; off >>= 1) s += __shfl_down_sync(0xffu, s, off);
        if (threadIdx.x == 0) g_pool[t*B*C + b*C + c] = s * (1.f / NPIX);
    }
}

__global__ __launch_bounds__(512) void chgemm(const float* __restrict__ qw,
                                              const float* __restrict__ kw) {
    int t = blockIdx.y, b = blockIdx.x;
    const float* wm = t ? kw : qw;
    __shared__ float ps[512];
    ps[threadIdx.x] = g_pool[t*B*C + b*C + threadIdx.x];
    __syncthreads();
    int o = threadIdx.x;
    float acc = 0.f;
    for (int c2 = 0; c2 < 512; c2++) acc = fmaf(ps[c2], wm[o*512 + c2], acc);
    g_cs[t*B*C + b*C + o] = acc_sigmoid(acc);
}

// ---------------- kv state + k_mean per (b, head) --------------------------
__global__ __launch_bounds__(1024) void kv_kernel(const float* __restrict__ x) {
    int h = blockIdx.x, b = blockIdx.y;
    int c0 = h * HD, jg0 = h * 16;
    __shared__ float kt[32][129];
    __shared__ float vt[32][129];
    int tid = threadIdx.x;
    int d = tid >> 5, e = tid & 31;
    const float* gate = g_gate + B*NPIX + b*NPIX;   // k side
    float acc = 0.f;
    double km = 0.0;
    for (int t0 = 0; t0 < NPIX; t0 += 128) {
        #pragma unroll
        for (int i = 0; i < 4; i++) {
            int lin = tid + i*1024;
            int dd = lin >> 7, col = lin & 127;
            int n = t0 + col;
            float v = g_kn[((size_t)(b*C + c0 + dd))*NPIX + n]
                      * gate[n] * g_cs[B*C + b*C + c0 + dd];
            kt[dd][col] = elu1(v);            // elu + 1
        }
        #pragma unroll
        for (int i = 0; i < 4; i++) {
            int lin = tid + i*1024;
            int col = lin >> 5, ee = lin & 31;
            vt[ee][col] = x[((size_t)(b*NPIX + t0 + col))*C + c0 + ee];
        }
        __syncthreads();
        #pragma unroll
        for (int i = 0; i < 2; i++) {
            int lin = tid + i*1024;
            int j = lin >> 7, col = lin & 127;
            float cv = g_cosT[(jg0 + j)*NPIX + t0 + col];
            float sv = g_sinT[(jg0 + j)*NPIX + t0 + col];
            float xr = kt[2*j][col], xi = kt[2*j+1][col];
            kt[2*j][col]   = cv*xr - sv*xi;
            kt[2*j+1][col] = sv*xr + cv*xi;
        }
        __syncthreads();
        #pragma unroll 8
        for (int col = 0; col < 128; col++) {
            float kd = kt[d][col];
            acc = fmaf(kd, vt[e][col], acc);
            km += (double)kd;
        }
        __syncthreads();
    }
    g_kv[((size_t)((b*HEADS + h)*HD + d))*HD + e] = acc * (1.f / NPIX);
    if (e == 0) g_km[(b*HEADS + h)*HD + d] = (float)(km * (1.0 / NPIX));
}

// ---------------- output: q_rope @ kv * z + lepe ---------------------------
__global__ __launch_bounds__(256) void out_kernel(const float* __restrict__ x,
        const float* __restrict__ lw, const float* __restrict__ lb,
        float* __restrict__ out) {
    int n0 = blockIdx.x * 128;
    int h = blockIdx.y, b = blockIdx.z;
    int c0 = h * HD, jg0 = h * 16;
    __shared__ float qt[32][129];
    __shared__ float kvs[32][32];
    __shared__ float kms[32];
    int tid = threadIdx.x;
    const float* gate = g_gate + b*NPIX;  // q side
    #pragma unroll
    for (int i = 0; i < 16; i++) {
        int lin = tid + i*256;
        int dd = lin >> 7, col = lin & 127;
        int n = n0 + col;
        float v = g_qn[((size_t)(b*C + c0 + dd))*NPIX + n]
                  * gate[n] * g_cs[b*C + c0 + dd];
        qt[dd][col] = elu1(v);
    }
    #pragma unroll
    for (int i = 0; i < 4; i++) {
        int lin = tid + i*256;
        kvs[lin >> 5][lin & 31] = g_kv[((size_t)(b*HEADS + h))*HD*HD + lin];
    }
    if (tid < 32) kms[tid] = g_km[(b*HEADS + h)*HD + tid];
    __syncthreads();
    #pragma unroll
    for (int i = 0; i < 8; i++) {
        int lin = tid + i*256;
        int j = lin >> 7, col = lin & 127;
        float cv = g_cosT[(jg0 + j)*NPIX + n0 + col];
        float sv = g_sinT[(jg0 + j)*NPIX + n0 + col];
        float xr = qt[2*j][col], xi = qt[2*j+1][col];
        qt[2*j][col]   = cv*xr - sv*xi;
        qt[2*j+1][col] = sv*xr + cv*xi;
    }
    __syncthreads();

    int e = tid & 31;
    int grp = tid >> 5;      // 0..7, each handles 16 columns
    int c = c0 + e;
    float wloc[9];
    #pragma unroll
    for (int i2 = 0; i2 < 9; i2++) wloc[i2] = lw[c*9 + i2];
    float lbv = lb[c];

    for (int ci = 0; ci < 16; ci++) {
        int col = grp*16 + ci;
        int n = n0 + col;
        float a1 = 0.f;
        double a2 = 0.0;
        #pragma unroll
        for (int dd = 0; dd < 32; dd++) {
            float qv = qt[dd][col];
            a1 = fmaf(qv, kvs[dd][e], a1);
            a2 += (double)qv * (double)kms[dd];
        }
        float z = 1.f / ((float)a2 + 1e-6f);
        float att = a1 * z;
        int hh = n >> 6, ww2 = n & 63;
        float lep = lbv;
        #pragma unroll
        for (int kh = 0; kh < 3; kh++) {
            int rr = hh + kh - 1;
            if (rr < 0 || rr >= 64) continue;
            #pragma unroll
            for (int kw = 0; kw < 3; kw++) {
                int cc2 = ww2 + kw - 1;
                if (cc2 < 0 || cc2 >= 64) continue;
                lep = fmaf(wloc[kh*3 + kw],
                           x[((size_t)(b*NPIX + rr*64 + cc2))*C + c], lep);
            }
        }
        out[((size_t)(b*NPIX + n))*C + c] = att + lep;
    }
}

// ---------------- launch ----------------------------------------------------
extern "C" void kernel_launch(void* const* d_in, const int* in_sizes, int n_in,
                              void* d_out, int out_size) {
    const float* x        = (const float*)d_in[0];
    const float* qk_w     = (const float*)d_in[1];
    const float* qk_b     = (const float*)d_in[2];
    const float* qsp_dw_w = (const float*)d_in[3];
    const float* qsp_dw_b = (const float*)d_in[4];
    const float* qsp_bn_g = (const float*)d_in[5];
    const float* qsp_bn_b = (const float*)d_in[6];
    const float* qsp_pw_w = (const float*)d_in[7];
    const float* qch_w    = (const float*)d_in[8];
    const float* ksp_dw_w = (const float*)d_in[9];
    const float* ksp_dw_b = (const float*)d_in[10];
    const float* ksp_bn_g = (const float*)d_in[11];
    const float* ksp_bn_b = (const float*)d_in[12];
    const float* ksp_pw_w = (const float*)d_in[13];
    const float* kch_w    = (const float*)d_in[14];
    const float* lepe_w   = (const float*)d_in[15];
    const float* lepe_b   = (const float*)d_in[16];
    const float* rope_cos = (const float*)d_in[17];
    const float* rope_sin = (const float*)d_in[18];
    float* out = (float*)d_out;

    repack_rope<<<4096, 256>>>(rope_cos, rope_sin);
    zero_gate<<<(2*B*NPIX + 255)/256, 256>>>();
    gemm_qk<<<dim3(16, 256), 256>>>(x, qk_w, qk_b);
    gate_accum<<<dim3(16, 8, B), 256>>>(0, qsp_dw_w, qsp_dw_b, qsp_bn_g, qsp_bn_b, qsp_pw_w);
    gate_accum<<<dim3(16, 8, B), 256>>>(1, ksp_dw_w, ksp_dw_b, ksp_bn_g, ksp_bn_b, ksp_pw_w);
    gate_sigmoid<<<(2*B*NPIX + 255)/256, 256>>>();
    pool_kernel<<<dim3(C, B, 2), 256>>>();
    chgemm<<<dim3(B, 2), 512>>>(qch_w, kch_w);
    kv_kernel<<<dim3(HEADS, B), 1024>>>(x);
    out_kernel<<<dim3(32, HEADS, B), 256>>>(x, lepe_w, lepe_b, out);
}

// round 3
// speedup vs baseline: 2.6580x; 2.6580x over previous
#include <cuda_runtime.h>
#include <math.h>

#define B 8
#define NPIX 4096
#define C 512
#define HEADS 16
#define HD 32

// ---------------- scratch (device globals; no runtime allocation) ----------
__device__ float g_qn[B*C*NPIX];        // q projection, (b,c,n) layout
__device__ float g_kn[B*C*NPIX];        // k projection, (b,c,n) layout
__device__ float g_gate[2*B*NPIX];      // spatial gate logits -> sigmoid (q then k)
__device__ float g_pool[2*B*C];
__device__ float g_cs[2*B*C];           // channel gate (q then k)
__device__ float g_cosT[256*NPIX];      // rope cos, (j, n) layout
__device__ float g_sinT[256*NPIX];
__device__ float g_kv[B*HEADS*HD*HD];
__device__ float g_km[B*HEADS*HD];
__device__ float g_fw[2*C*9];           // folded dwconv weights (w * bn_scale)
__device__ float g_fb[2*C];             // folded bias

__device__ __forceinline__ float acc_sigmoid(float x) {
    return 1.0f / (1.0f + expf(-x));
}
__device__ __forceinline__ float elu1(float x) {
    return x > 0.0f ? x + 1.0f : expf(x);
}

// ---------------- rope repack: (n,256) -> (256,n) ---------------------------
__global__ void repack_cos(const float* __restrict__ rc) {
    int idx = blockIdx.x * blockDim.x + threadIdx.x;
    int j = idx >> 12;
    int n = idx & 4095;
    g_cosT[idx] = rc[n*256 + j];
}
__global__ void repack_sin(const float* __restrict__ rs) {
    int idx = blockIdx.x * blockDim.x + threadIdx.x;
    int j = idx >> 12;
    int n = idx & 4095;
    g_sinT[idx] = rs[n*256 + j];
}

__global__ void zero_gate() {
    int i = blockIdx.x * blockDim.x + threadIdx.x;
    if (i < 2*B*NPIX) g_gate[i] = 0.f;
}

// ---------------- fold BN scale into dwconv weights -------------------------
__global__ void fold_gate(int which, const float* __restrict__ dww,
                          const float* __restrict__ dwb,
                          const float* __restrict__ bng,
                          const float* __restrict__ bnb) {
    int c = threadIdx.x;
    float gs = bng[c] * (1.0f / sqrtf(1.0f + 1e-5f));
    #pragma unroll
    for (int i = 0; i < 9; i++)
        g_fw[which*C*9 + c*9 + i] = dww[c*9 + i] * gs;
    g_fb[which*C + c] = dwb[c] * gs + bnb[c];
}

// ---------------- GEMM: qk = x @ qk_w^T + b, transposed store --------------
// M=32768, N=1024, K=512. BM=128, BN=128, BK=8, 256 thr, 8x8 micro, dbl-buf.
__global__ __launch_bounds__(256) void gemm_qk(const float* __restrict__ x,
                                               const float* __restrict__ w,
                                               const float* __restrict__ bias) {
    __shared__ __align__(16) float As[2][8][132];
    __shared__ __align__(16) float Bs[2][8][132];
    __shared__ __align__(16) float stage[128][33];

    const int tid = threadIdx.x;
    const int m0 = blockIdx.y * 128;
    const int o0 = blockIdx.x * 128;
    const int tr = tid >> 4;       // 0..15
    const int tc = tid & 15;       // 0..15

    const int lr = tid >> 1;          // 0..127
    const int lk = (tid & 1) * 4;     // 0 or 4

    const float* xp = x + (size_t)(m0 + lr) * 512 + lk;
    const float* wp = w + (size_t)(o0 + lr) * 512 + lk;

    // prologue: tile 0
    {
        float4 xa = *(const float4*)xp;
        float4 wb = *(const float4*)wp;
        As[0][lk+0][lr] = xa.x; As[0][lk+1][lr] = xa.y;
        As[0][lk+2][lr] = xa.z; As[0][lk+3][lr] = xa.w;
        Bs[0][lk+0][lr] = wb.x; Bs[0][lk+1][lr] = wb.y;
        Bs[0][lk+2][lr] = wb.z; Bs[0][lk+3][lr] = wb.w;
    }
    __syncthreads();

    float acc[8][8];
    #pragma unroll
    for (int i = 0; i < 8; i++)
        #pragma unroll
        for (int j = 0; j < 8; j++) acc[i][j] = 0.f;

    int buf = 0;
    for (int k0 = 0; k0 < 512; k0 += 8) {
        float4 nxa, nwb;
        const bool more = (k0 + 8 < 512);
        if (more) {
            nxa = *(const float4*)(xp + k0 + 8);
            nwb = *(const float4*)(wp + k0 + 8);
        }
        #pragma unroll
        for (int kk = 0; kk < 8; kk++) {
            float a[8], b[8];
            *(float4*)&a[0] = *(const float4*)&As[buf][kk][tr*4];
            *(float4*)&a[4] = *(const float4*)&As[buf][kk][64 + tr*4];
            *(float4*)&b[0] = *(const float4*)&Bs[buf][kk][tc*4];
            *(float4*)&b[4] = *(const float4*)&Bs[buf][kk][64 + tc*4];
            #pragma unroll
            for (int i = 0; i < 8; i++)
                #pragma unroll
                for (int j = 0; j < 8; j++)
                    acc[i][j] = fmaf(a[i], b[j], acc[i][j]);
        }
        if (more) {
            int nb = buf ^ 1;
            As[nb][lk+0][lr] = nxa.x; As[nb][lk+1][lr] = nxa.y;
            As[nb][lk+2][lr] = nxa.z; As[nb][lk+3][lr] = nxa.w;
            Bs[nb][lk+0][lr] = nwb.x; Bs[nb][lk+1][lr] = nwb.y;
            Bs[nb][lk+2][lr] = nwb.z; Bs[nb][lk+3][lr] = nwb.w;
            __syncthreads();
            buf = nb;
        }
    }

    // bias
    float bv[8];
    #pragma unroll
    for (int j = 0; j < 4; j++) {
        bv[j]   = bias[o0 + tc*4 + j];
        bv[j+4] = bias[o0 + 64 + tc*4 + j];
    }

    const int bimg = m0 >> 12;       // batch index (128 | 4096)
    const int nbase = m0 & 4095;

    // epilogue: 4 chunks of 32 output channels, staged transpose
    for (int ch = 0; ch < 4; ch++) {
        __syncthreads();
        // first-half cols (o-local 0..63) belong to ch 0,1 ; second half to 2,3
        if (ch < 2) {
            if ((tc >> 3) == ch) {
                int clbase = tc*4 - ch*32;
                #pragma unroll
                for (int i = 0; i < 4; i++)
                    #pragma unroll
                    for (int j = 0; j < 4; j++)
                        stage[tr*4 + i][clbase + j] = acc[i][j] + bv[j];
                #pragma unroll
                for (int i = 0; i < 4; i++)
                    #pragma unroll
                    for (int j = 0; j < 4; j++)
                        stage[64 + tr*4 + i][clbase + j] = acc[i+4][j] + bv[j];
            }
        } else {
            if ((tc >> 3) == (ch - 2)) {
                int clbase = tc*4 - (ch-2)*32;
                #pragma unroll
                for (int i = 0; i < 4; i++)
                    #pragma unroll
                    for (int j = 0; j < 4; j++)
                        stage[tr*4 + i][clbase + j] = acc[i][j+4] + bv[j+4];
                #pragma unroll
                for (int i = 0; i < 4; i++)
                    #pragma unroll
                    for (int j = 0; j < 4; j++)
                        stage[64 + tr*4 + i][clbase + j] = acc[i+4][j+4] + bv[j+4];
            }
        }
        __syncthreads();
        #pragma unroll
        for (int i = 0; i < 16; i++) {
            int lin = tid + i*256;
            int r  = lin & 127;
            int cl = lin >> 7;          // 0..31
            int o  = o0 + ch*32 + cl;
            float val = stage[r][cl];
            int n = nbase + r;
            if (o < 512) g_qn[((size_t)(bimg*C + o))*NPIX + n] = val;
            else         g_kn[((size_t)(bimg*C + (o-512)))*NPIX + n] = val;
        }
    }
}

// ---------------- spatial gate: dwconv(+folded BN)+relu, reduce over chans -
// block: 8 rows x 64 cols, 64-channel chunk; atomicAdd partials.
__global__ __launch_bounds__(512) void gate_accum(int which, const float* __restrict__ pww) {
    const float* src = which ? g_kn : g_qn;
    const float* fw = g_fw + which*C*9;
    const float* fb = g_fb + which*C;
    float* slog = g_gate + which * B * NPIX;
    int b  = blockIdx.z;
    int r0 = blockIdx.x * 8;
    int c0 = blockIdx.y * 64;
    int tid = threadIdx.x;
    int r  = tid >> 6;
    int wx = tid & 63;
    __shared__ float tile[10][64];
    float acc = 0.f;
    for (int c = c0; c < c0 + 64; c++) {
        const float* plane = src + ((size_t)(b*C + c)) * NPIX;
        #pragma unroll
        for (int lin = tid; lin < 640; lin += 512) {
            int rr = (lin >> 6) + r0 - 1;
            int cc = lin & 63;
            tile[lin >> 6][cc] = (rr >= 0 && rr < 64) ? plane[rr*64 + cc] : 0.f;
        }
        __syncthreads();
        float conv = fb[c];
        #pragma unroll
        for (int kh = 0; kh < 3; kh++) {
            #pragma unroll
            for (int kw = 0; kw < 3; kw++) {
                int cc = wx + kw - 1;
                float v = (cc >= 0 && cc < 64) ? tile[r + kh][cc] : 0.f;
                conv = fmaf(v, fw[c*9 + kh*3 + kw], conv);
            }
        }
        float y = fmaxf(conv, 0.f);
        acc = fmaf(y, pww[c], acc);
        __syncthreads();
    }
    atomicAdd(&slog[b*NPIX + (r0 + r)*64 + wx], acc);
}

__global__ void gate_sigmoid() {
    int i = blockIdx.x * blockDim.x + threadIdx.x;
    if (i < 2*B*NPIX) g_gate[i] = acc_sigmoid(g_gate[i]);
}

// ---------------- channel pool + SE gemm -----------------------------------
__global__ __launch_bounds__(256) void pool_kernel() {
    int t = blockIdx.z, b = blockIdx.y, c = blockIdx.x;
    const float* src  = t ? g_kn : g_qn;
    const float* gate = g_gate + t*B*NPIX + b*NPIX;
    const float* plane = src + ((size_t)(b*C + c)) * NPIX;
    float s = 0.f;
    for (int n = threadIdx.x; n < NPIX; n += 256) s = fmaf(plane[n], gate[n], s);
    __shared__ float red[8];
    for (int off = 16; off; off >>= 1) s += __shfl_down_sync(0xffffffffu, s, off);
    if ((threadIdx.x & 31) == 0) red[threadIdx.x >> 5] = s;
    __syncthreads();
    if (threadIdx.x < 8) {
        s = red[threadIdx.x];
        for (int off = 4; off; off >>= 1) s += __shfl_down_sync(0xffu, s, off);
        if (threadIdx.x == 0) g_pool[t*B*C + b*C + c] = s * (1.f / NPIX);
    }
}

__global__ __launch_bounds__(512) void chgemm(const float* __restrict__ qw,
                                              const float* __restrict__ kw) {
    int t = blockIdx.y, b = blockIdx.x;
    const float* wm = t ? kw : qw;
    __shared__ float ps[512];
    ps[threadIdx.x] = g_pool[t*B*C + b*C + threadIdx.x];
    __syncthreads();
    int o = threadIdx.x;
    float acc = 0.f;
    for (int c2 = 0; c2 < 512; c2++) acc = fmaf(ps[c2], wm[o*512 + c2], acc);
    g_cs[t*B*C + b*C + o] = acc_sigmoid(acc);
}

// ---------------- kv state + k_mean per (b, head) --------------------------
__global__ __launch_bounds__(1024) void kv_kernel(const float* __restrict__ x) {
    int h = blockIdx.x, b = blockIdx.y;
    int c0 = h * HD, jg0 = h * 16;
    __shared__ float kt[32][129];
    __shared__ float vt[32][129];
    int tid = threadIdx.x;
    int d = tid >> 5, e = tid & 31;
    const float* gate = g_gate + B*NPIX + b*NPIX;   // k side
    float acc = 0.f;
    double kmd = 0.0;
    for (int t0 = 0; t0 < NPIX; t0 += 128) {
        #pragma unroll
        for (int i = 0; i < 4; i++) {
            int lin = tid + i*1024;
            int dd = lin >> 7, col = lin & 127;
            int n = t0 + col;
            float v = g_kn[((size_t)(b*C + c0 + dd))*NPIX + n]
                      * gate[n] * g_cs[B*C + b*C + c0 + dd];
            kt[dd][col] = elu1(v);            // elu + 1
        }
        #pragma unroll
        for (int i = 0; i < 4; i++) {
            int lin = tid + i*1024;
            int col = lin >> 5, ee = lin & 31;
            vt[ee][col] = x[((size_t)(b*NPIX + t0 + col))*C + c0 + ee];
        }
        __syncthreads();
        #pragma unroll
        for (int i = 0; i < 2; i++) {
            int lin = tid + i*1024;
            int j = lin >> 7, col = lin & 127;
            float cv = g_cosT[(jg0 + j)*NPIX + t0 + col];
            float sv = g_sinT[(jg0 + j)*NPIX + t0 + col];
            float xr = kt[2*j][col], xi = kt[2*j+1][col];
            kt[2*j][col]   = cv*xr - sv*xi;
            kt[2*j+1][col] = sv*xr + cv*xi;
        }
        __syncthreads();
        float kmf = 0.f;
        #pragma unroll 8
        for (int col = 0; col < 128; col++) {
            float kd = kt[d][col];
            acc = fmaf(kd, vt[e][col], acc);
            kmf += kd;
        }
        kmd += (double)kmf;
        __syncthreads();
    }
    g_kv[((size_t)((b*HEADS + h)*HD + d))*HD + e] = acc * (1.f / NPIX);
    if (e == 0) g_km[(b*HEADS + h)*HD + d] = (float)(kmd * (1.0 / NPIX));
}

// ---------------- output: q_rope @ kv * z + lepe ---------------------------
__global__ __launch_bounds__(256) void out_kernel(const float* __restrict__ x,
        const float* __restrict__ lw, const float* __restrict__ lb,
        float* __restrict__ out) {
    int n0 = blockIdx.x * 128;
    int h = blockIdx.y, b = blockIdx.z;
    int c0 = h * HD, jg0 = h * 16;
    __shared__ float qt[32][129];
    __shared__ float kvs[32][32];
    __shared__ float kms[32];
    __shared__ float xs[4][64][32];     // x rows hh0-1..hh0+2, 32 chans of head
    int tid = threadIdx.x;
    int hh0 = n0 >> 6;
    const float* gate = g_gate + b*NPIX;  // q side
    #pragma unroll
    for (int i = 0; i < 16; i++) {
        int lin = tid + i*256;
        int dd = lin >> 7, col = lin & 127;
        int n = n0 + col;
        float v = g_qn[((size_t)(b*C + c0 + dd))*NPIX + n]
                  * gate[n] * g_cs[b*C + c0 + dd];
        qt[dd][col] = elu1(v);
    }
    #pragma unroll
    for (int i = 0; i < 32; i++) {
        int lin = tid + i*256;            // < 8192
        int cch  = lin & 31;
        int ccol = (lin >> 5) & 63;
        int ri   = lin >> 11;             // 0..3
        int rr = hh0 - 1 + ri;
        xs[ri][ccol][cch] = (rr >= 0 && rr < 64)
            ? x[((size_t)(b*NPIX + rr*64 + ccol))*C + c0 + cch] : 0.f;
    }
    #pragma unroll
    for (int i = 0; i < 4; i++) {
        int lin = tid + i*256;
        kvs[lin >> 5][lin & 31] = g_kv[((size_t)(b*HEADS + h))*HD*HD + lin];
    }
    if (tid < 32) kms[tid] = g_km[(b*HEADS + h)*HD + tid];
    __syncthreads();
    #pragma unroll
    for (int i = 0; i < 8; i++) {
        int lin = tid + i*256;
        int j = lin >> 7, col = lin & 127;
        float cv = g_cosT[(jg0 + j)*NPIX + n0 + col];
        float sv = g_sinT[(jg0 + j)*NPIX + n0 + col];
        float xr = qt[2*j][col], xi = qt[2*j+1][col];
        qt[2*j][col]   = cv*xr - sv*xi;
        qt[2*j+1][col] = sv*xr + cv*xi;
    }
    __syncthreads();

    int e = tid & 31;
    int grp = tid >> 5;      // 0..7, each handles 16 columns
    int c = c0 + e;
    float wloc[9];
    #pragma unroll
    for (int i2 = 0; i2 < 9; i2++) wloc[i2] = lw[c*9 + i2];
    float lbv = lb[c];

    for (int ci = 0; ci < 16; ci++) {
        int col = grp*16 + ci;
        int n = n0 + col;
        float a1 = 0.f;
        // Kahan + TwoProdFMA for the denominator dot (fp64-quality in fp32)
        float s2 = 0.f, cmp = 0.f, pe = 0.f;
        #pragma unroll
        for (int dd = 0; dd < 32; dd++) {
            float qv = qt[dd][col];
            a1 = fmaf(qv, kvs[dd][e], a1);
            float kmv = kms[dd];
            float p = qv * kmv;
            pe += fmaf(qv, kmv, -p);
            float yy = p - cmp;
            float tt = s2 + yy;
            cmp = (tt - s2) - yy;
            s2 = tt;
        }
        float a2 = s2 + pe;
        float z = 1.f / (a2 + 1e-6f);
        float att = a1 * z;
        int hh = n >> 6, ww2 = n & 63;
        int rbase = hh - hh0;   // 0 or 1
        float lep = lbv;
        #pragma unroll
        for (int kh = 0; kh < 3; kh++) {
            #pragma unroll
            for (int kw = 0; kw < 3; kw++) {
                int cc2 = ww2 + kw - 1;
                if (cc2 < 0 || cc2 >= 64) continue;
                lep = fmaf(wloc[kh*3 + kw], xs[rbase + kh][cc2][e], lep);
            }
        }
        out[((size_t)(b*NPIX + n))*C + c] = att + lep;
    }
}

// ---------------- launch ----------------------------------------------------
extern "C" void kernel_launch(void* const* d_in, const int* in_sizes, int n_in,
                              void* d_out, int out_size) {
    const float* x        = (const float*)d_in[0];
    const float* qk_w     = (const float*)d_in[1];
    const float* qk_b     = (const float*)d_in[2];
    const float* qsp_dw_w = (const float*)d_in[3];
    const float* qsp_dw_b = (const float*)d_in[4];
    const float* qsp_bn_g = (const float*)d_in[5];
    const float* qsp_bn_b = (const float*)d_in[6];
    const float* qsp_pw_w = (const float*)d_in[7];
    const float* qch_w    = (const float*)d_in[8];
    const float* ksp_dw_w = (const float*)d_in[9];
    const float* ksp_dw_b = (const float*)d_in[10];
    const float* ksp_bn_g = (const float*)d_in[11];
    const float* ksp_bn_b = (const float*)d_in[12];
    const float* ksp_pw_w = (const float*)d_in[13];
    const float* kch_w    = (const float*)d_in[14];
    const float* lepe_w   = (const float*)d_in[15];
    const float* lepe_b   = (const float*)d_in[16];
    const float* rope_cos = (const float*)d_in[17];
    const float* rope_sin = (const float*)d_in[18];
    float* out = (float*)d_out;

    repack_cos<<<4096, 256>>>(rope_cos);                               // 1
    repack_sin<<<4096, 256>>>(rope_sin);                               // 2
    zero_gate<<<(2*B*NPIX + 255)/256, 256>>>();                        // 3
    fold_gate<<<1, 512>>>(0, qsp_dw_w, qsp_dw_b, qsp_bn_g, qsp_bn_b);  // 4
    fold_gate<<<1, 512>>>(1, ksp_dw_w, ksp_dw_b, ksp_bn_g, ksp_bn_b);  // 5
    gemm_qk<<<dim3(8, 256), 256>>>(x, qk_w, qk_b);                     // 6 (profiled)
    gate_accum<<<dim3(8, 8, B), 512>>>(0, qsp_pw_w);                   // 7
    gate_accum<<<dim3(8, 8, B), 512>>>(1, ksp_pw_w);                   // 8
    gate_sigmoid<<<(2*B*NPIX + 255)/256, 256>>>();                     // 9
    pool_kernel<<<dim3(C, B, 2), 256>>>();                             // 10
    chgemm<<<dim3(B, 2), 512>>>(qch_w, kch_w);                         // 11
    kv_kernel<<<dim3(HEADS, B), 1024>>>(x);                            // 12
    out_kernel<<<dim3(32, HEADS, B), 256>>>(x, lepe_w, lepe_b, out);   // 13
}

// round 9
// speedup vs baseline: 3.7749x; 1.4202x over previous
#include <cuda_runtime.h>
#include <math.h>
#include <cstdint>

#define B 8
#define NPIX 4096
#define C 512
#define HEADS 16
#define HD 32

// ---------------- scratch (device globals; no runtime allocation) ----------
__device__ float g_qn[B*C*NPIX];        // q projection, (b,c,n) layout
__device__ float g_kn[B*C*NPIX];        // k projection, (b,c,n) layout
__device__ float g_gate[2*B*NPIX];      // spatial gate logits -> sigmoid (q then k)
__device__ float g_pool[2*B*C];
__device__ float g_cs[2*B*C];           // channel gate (q then k)
__device__ float g_cosT[256*NPIX];      // rope cos, (j, n) layout
__device__ float g_sinT[256*NPIX];
__device__ float g_kv[B*HEADS*HD*HD];
__device__ float g_km[B*HEADS*HD];
__device__ float g_fw[2*C*9];           // folded dwconv weights (w * bn_scale)
__device__ float g_fb[2*C];             // folded bias
// tf32 2-way split of the K half of qk_w (rows 512..1023)
__device__ __align__(16) float g_wa[C*C];
__device__ __align__(16) float g_wb[C*C];

__device__ __forceinline__ float acc_sigmoid(float x) {
    return 1.0f / (1.0f + expf(-x));
}
__device__ __forceinline__ float elu1(float x) {
    return x > 0.0f ? x + 1.0f : expf(x);
}
__device__ __forceinline__ float tf32mask(float v) {
    return __uint_as_float(__float_as_uint(v) & 0xFFFFE000u);
}
__device__ __forceinline__ void mma8(float* c, const uint32_t* a, const uint32_t* b) {
    asm volatile("mma.sync.aligned.m16n8k8.row.col.f32.tf32.tf32.f32 "
        "{%0,%1,%2,%3}, {%4,%5,%6,%7}, {%8,%9}, {%0,%1,%2,%3};"
        : "+f"(c[0]), "+f"(c[1]), "+f"(c[2]), "+f"(c[3])
        : "r"(a[0]), "r"(a[1]), "r"(a[2]), "r"(a[3]), "r"(b[0]), "r"(b[1]));
}

// ---------------- rope repack: (n,256) -> (256,n) ---------------------------
__global__ void repack_cos(const float* __restrict__ rc) {
    int idx = blockIdx.x * blockDim.x + threadIdx.x;
    int j = idx >> 12;
    int n = idx & 4095;
    g_cosT[idx] = rc[n*256 + j];
}
__global__ void repack_sin(const float* __restrict__ rs) {
    int idx = blockIdx.x * blockDim.x + threadIdx.x;
    int j = idx >> 12;
    int n = idx & 4095;
    g_sinT[idx] = rs[n*256 + j];
}

// ---------------- zero gate + fold BN into dwconv ---------------------------
__global__ void setup_misc(const float* __restrict__ qdww, const float* __restrict__ qdwb,
                           const float* __restrict__ qbng, const float* __restrict__ qbnb,
                           const float* __restrict__ kdww, const float* __restrict__ kdwb,
                           const float* __restrict__ kbng, const float* __restrict__ kbnb) {
    int bx = blockIdx.x;
    if (bx < 128) {
        g_gate[bx*512 + threadIdx.x] = 0.f;
    } else {
        int which = bx - 128;
        int c = threadIdx.x;
        const float* dww = which ? kdww : qdww;
        const float* dwb = which ? kdwb : qdwb;
        const float* bng = which ? kbng : qbng;
        const float* bnb = which ? kbnb : qbnb;
        float gs = bng[c] * (1.0f / sqrtf(1.0f + 1e-5f));
        #pragma unroll
        for (int i = 0; i < 9; i++)
            g_fw[which*C*9 + c*9 + i] = dww[c*9 + i] * gs;
        g_fb[which*C + c] = dwb[c] * gs + bnb[c];
    }
}

// ---------------- 2-way mask split of the K weight half ---------------------
__global__ void split_wk(const float* __restrict__ w) {
    int i = blockIdx.x * 256 + threadIdx.x;     // 0 .. C*C-1
    float v = w[(size_t)C*C + i];               // k rows start at 512
    float a = tf32mask(v);
    g_wa[i] = a;
    g_wb[i] = tf32mask(v - a);                  // v - a exact
}

// ---------------- Q GEMM: SIMT fp32 (proven numerics from R3) ---------------
// q = x @ qk_w[:512]^T + b[:512]. M=32768, N=512, K=512.
// BM=128, BN=128, BK=8, 256 thr, 8x8 micro, dbl-buf.
__global__ __launch_bounds__(256) void gemm_q(const float* __restrict__ x,
                                              const float* __restrict__ w,
                                              const float* __restrict__ bias) {
    __shared__ __align__(16) float As[2][8][132];
    __shared__ __align__(16) float Bs[2][8][132];
    __shared__ __align__(16) float stage[128][33];

    const int tid = threadIdx.x;
    const int m0 = blockIdx.y * 128;
    const int o0 = blockIdx.x * 128;       // 0..384 (q half only)
    const int tr = tid >> 4;
    const int tc = tid & 15;

    const int lr = tid >> 1;
    const int lk = (tid & 1) * 4;

    const float* xp = x + (size_t)(m0 + lr) * 512 + lk;
    const float* wp = w + (size_t)(o0 + lr) * 512 + lk;

    {
        float4 xa = *(const float4*)xp;
        float4 wb = *(const float4*)wp;
        As[0][lk+0][lr] = xa.x; As[0][lk+1][lr] = xa.y;
        As[0][lk+2][lr] = xa.z; As[0][lk+3][lr] = xa.w;
        Bs[0][lk+0][lr] = wb.x; Bs[0][lk+1][lr] = wb.y;
        Bs[0][lk+2][lr] = wb.z; Bs[0][lk+3][lr] = wb.w;
    }
    __syncthreads();

    float acc[8][8];
    #pragma unroll
    for (int i = 0; i < 8; i++)
        #pragma unroll
        for (int j = 0; j < 8; j++) acc[i][j] = 0.f;

    int buf = 0;
    for (int k0 = 0; k0 < 512; k0 += 8) {
        float4 nxa, nwb;
        const bool more = (k0 + 8 < 512);
        if (more) {
            nxa = *(const float4*)(xp + k0 + 8);
            nwb = *(const float4*)(wp + k0 + 8);
        }
        #pragma unroll
        for (int kk = 0; kk < 8; kk++) {
            float a[8], b[8];
            *(float4*)&a[0] = *(const float4*)&As[buf][kk][tr*4];
            *(float4*)&a[4] = *(const float4*)&As[buf][kk][64 + tr*4];
            *(float4*)&b[0] = *(const float4*)&Bs[buf][kk][tc*4];
            *(float4*)&b[4] = *(const float4*)&Bs[buf][kk][64 + tc*4];
            #pragma unroll
            for (int i = 0; i < 8; i++)
                #pragma unroll
                for (int j = 0; j < 8; j++)
                    acc[i][j] = fmaf(a[i], b[j], acc[i][j]);
        }
        if (more) {
            int nb = buf ^ 1;
            As[nb][lk+0][lr] = nxa.x; As[nb][lk+1][lr] = nxa.y;
            As[nb][lk+2][lr] = nxa.z; As[nb][lk+3][lr] = nxa.w;
            Bs[nb][lk+0][lr] = nwb.x; Bs[nb][lk+1][lr] = nwb.y;
            Bs[nb][lk+2][lr] = nwb.z; Bs[nb][lk+3][lr] = nwb.w;
            __syncthreads();
            buf = nb;
        }
    }

    float bv[8];
    #pragma unroll
    for (int j = 0; j < 4; j++) {
        bv[j]   = bias[o0 + tc*4 + j];
        bv[j+4] = bias[o0 + 64 + tc*4 + j];
    }

    const int bimg = m0 >> 12;
    const int nbase = m0 & 4095;

    for (int ch = 0; ch < 4; ch++) {
        __syncthreads();
        if (ch < 2) {
            if ((tc >> 3) == ch) {
                int clbase = tc*4 - ch*32;
                #pragma unroll
                for (int i = 0; i < 4; i++)
                    #pragma unroll
                    for (int j = 0; j < 4; j++)
                        stage[tr*4 + i][clbase + j] = acc[i][j] + bv[j];
                #pragma unroll
                for (int i = 0; i < 4; i++)
                    #pragma unroll
                    for (int j = 0; j < 4; j++)
                        stage[64 + tr*4 + i][clbase + j] = acc[i+4][j] + bv[j];
            }
        } else {
            if ((tc >> 3) == (ch - 2)) {
                int clbase = tc*4 - (ch-2)*32;
                #pragma unroll
                for (int i = 0; i < 4; i++)
                    #pragma unroll
                    for (int j = 0; j < 4; j++)
                        stage[tr*4 + i][clbase + j] = acc[i][j+4] + bv[j+4];
                #pragma unroll
                for (int i = 0; i < 4; i++)
                    #pragma unroll
                    for (int j = 0; j < 4; j++)
                        stage[64 + tr*4 + i][clbase + j] = acc[i+4][j+4] + bv[j+4];
            }
        }
        __syncthreads();
        #pragma unroll
        for (int i = 0; i < 16; i++) {
            int lin = tid + i*256;
            int r  = lin & 127;
            int cl = lin >> 7;
            int o  = o0 + ch*32 + cl;
            int n = nbase + r;
            g_qn[((size_t)(bimg*C + o))*NPIX + n] = stage[r][cl];
        }
    }
}

// ---------------- K GEMM: tf32 MMA, 2-way split, 4 products -----------------
// k = x @ qk_w[512:]^T + b[512:]. M=32768, N=512, K=512.
// BM=128, BN=128, BK=16, 256 thr (8 warps: 2m x 4n), warp tile 64x32.
#define GT_P 17
#define GT_T (128*GT_P)

__global__ __launch_bounds__(256) void gemm_k(const float* __restrict__ x,
                                              const float* __restrict__ bias) {
    __shared__ __align__(16) float sm[4*GT_T];
    float* As0 = sm;
    float* As1 = sm + GT_T;
    float* Bs0 = sm + 2*GT_T;
    float* Bs1 = sm + 3*GT_T;
    float* stage = sm;

    const int tid = threadIdx.x;
    const int wid = tid >> 5;
    const int lane = tid & 31;
    const int warp_m = wid >> 2;
    const int warp_n = wid & 3;
    const int m0 = blockIdx.y * 128;
    const int o0 = blockIdx.x * 128;       // k-local 0..384
    const int bg = lane >> 2;
    const int tig = lane & 3;

    float acc[4][4][4];
    #pragma unroll
    for (int mt = 0; mt < 4; mt++)
        #pragma unroll
        for (int nt = 0; nt < 4; nt++)
            #pragma unroll
            for (int r = 0; r < 4; r++) acc[mt][nt][r] = 0.f;

    const int r0l = tid >> 2;         // 0..63
    const int r1l = r0l + 64;
    const int ql = tid & 3;

    float4 av[2], bav[2], bbv[2];

    av[0]  = *(const float4*)(x    + (size_t)(m0 + r0l)*512 + ql*4);
    av[1]  = *(const float4*)(x    + (size_t)(m0 + r1l)*512 + ql*4);
    bav[0] = *(const float4*)(g_wa + (size_t)(o0 + r0l)*512 + ql*4);
    bav[1] = *(const float4*)(g_wa + (size_t)(o0 + r1l)*512 + ql*4);
    bbv[0] = *(const float4*)(g_wb + (size_t)(o0 + r0l)*512 + ql*4);
    bbv[1] = *(const float4*)(g_wb + (size_t)(o0 + r1l)*512 + ql*4);

    for (int ch = 0; ch < 32; ch++) {
        #pragma unroll
        for (int i = 0; i < 2; i++) {
            int row = i ? r1l : r0l;
            float va[4] = {av[i].x, av[i].y, av[i].z, av[i].w};
            float wa[4] = {bav[i].x, bav[i].y, bav[i].z, bav[i].w};
            float wb[4] = {bbv[i].x, bbv[i].y, bbv[i].z, bbv[i].w};
            #pragma unroll
            for (int j = 0; j < 4; j++) {
                float a1 = tf32mask(va[j]);
                As0[row*GT_P + ql*4 + j] = a1;
                As1[row*GT_P + ql*4 + j] = tf32mask(va[j] - a1);
                Bs0[row*GT_P + ql*4 + j] = wa[j];
                Bs1[row*GT_P + ql*4 + j] = wb[j];
            }
        }
        __syncthreads();

        if (ch < 31) {
            int kc = (ch + 1) * 16;
            av[0]  = *(const float4*)(x    + (size_t)(m0 + r0l)*512 + kc + ql*4);
            av[1]  = *(const float4*)(x    + (size_t)(m0 + r1l)*512 + kc + ql*4);
            bav[0] = *(const float4*)(g_wa + (size_t)(o0 + r0l)*512 + kc + ql*4);
            bav[1] = *(const float4*)(g_wa + (size_t)(o0 + r1l)*512 + kc + ql*4);
            bbv[0] = *(const float4*)(g_wb + (size_t)(o0 + r0l)*512 + kc + ql*4);
            bbv[1] = *(const float4*)(g_wb + (size_t)(o0 + r1l)*512 + kc + ql*4);
        }

        #pragma unroll
        for (int k8 = 0; k8 < 16; k8 += 8) {
            uint32_t Bf0[4][2], Bf1[4][2];
            #pragma unroll
            for (int nt = 0; nt < 4; nt++) {
                int brow = warp_n*32 + nt*8 + bg;
                int bq = tig + k8;
                Bf0[nt][0] = __float_as_uint(Bs0[brow*GT_P + bq]);
                Bf0[nt][1] = __float_as_uint(Bs0[brow*GT_P + bq + 4]);
                Bf1[nt][0] = __float_as_uint(Bs1[brow*GT_P + bq]);
                Bf1[nt][1] = __float_as_uint(Bs1[brow*GT_P + bq + 4]);
            }
            #pragma unroll
            for (int mt = 0; mt < 4; mt++) {
                int arow = warp_m*64 + mt*16 + bg;
                int aq = tig + k8;
                uint32_t Af0[4], Af1[4];
                Af0[0] = __float_as_uint(As0[arow*GT_P + aq]);
                Af0[1] = __float_as_uint(As0[(arow+8)*GT_P + aq]);
                Af0[2] = __float_as_uint(As0[arow*GT_P + aq + 4]);
                Af0[3] = __float_as_uint(As0[(arow+8)*GT_P + aq + 4]);
                Af1[0] = __float_as_uint(As1[arow*GT_P + aq]);
                Af1[1] = __float_as_uint(As1[(arow+8)*GT_P + aq]);
                Af1[2] = __float_as_uint(As1[arow*GT_P + aq + 4]);
                Af1[3] = __float_as_uint(As1[(arow+8)*GT_P + aq + 4]);
                #pragma unroll
                for (int nt = 0; nt < 4; nt++) {
                    mma8(acc[mt][nt], Af0, Bf0[nt]);
                    mma8(acc[mt][nt], Af0, Bf1[nt]);
                    mma8(acc[mt][nt], Af1, Bf0[nt]);
                    mma8(acc[mt][nt], Af1, Bf1[nt]);
                }
            }
        }
        __syncthreads();
    }

    const int bimg = m0 >> 12;
    const int nbase = m0 & 4095;
    for (int ch = 0; ch < 4; ch++) {
        if (warp_n == ch) {
            #pragma unroll
            for (int mt = 0; mt < 4; mt++) {
                int row = warp_m*64 + mt*16 + bg;
                #pragma unroll
                for (int nt = 0; nt < 4; nt++) {
                    int col = nt*8 + tig*2;
                    stage[row*33 + col]       = acc[mt][nt][0];
                    stage[row*33 + col + 1]   = acc[mt][nt][1];
                    stage[(row+8)*33 + col]   = acc[mt][nt][2];
                    stage[(row+8)*33 + col+1] = acc[mt][nt][3];
                }
            }
        }
        __syncthreads();
        #pragma unroll
        for (int i = 0; i < 16; i++) {
            int lin = tid + i*256;
            int m = lin & 127;
            int ol = lin >> 7;
            int o = o0 + ch*32 + ol;            // k-local channel
            float val = stage[m*33 + ol] + bias[512 + o];
            int n = nbase + m;
            g_kn[((size_t)(bimg*C + o))*NPIX + n] = val;
        }
        __syncthreads();
    }
}

// ---------------- spatial gate: dwconv(+folded BN)+relu, reduce over chans -
__global__ __launch_bounds__(512) void gate_accum(int which, const float* __restrict__ pww) {
    const float* src = which ? g_kn : g_qn;
    const float* fw = g_fw + which*C*9;
    const float* fb = g_fb + which*C;
    float* slog = g_gate + which * B * NPIX;
    int b  = blockIdx.z;
    int r0 = blockIdx.x * 8;
    int c0 = blockIdx.y * 64;
    int tid = threadIdx.x;
    int r  = tid >> 6;
    int wx = tid & 63;
    __shared__ float tile[10][64];
    float acc = 0.f;
    for (int c = c0; c < c0 + 64; c++) {
        const float* plane = src + ((size_t)(b*C + c)) * NPIX;
        #pragma unroll
        for (int lin = tid; lin < 640; lin += 512) {
            int rr = (lin >> 6) + r0 - 1;
            int cc = lin & 63;
            tile[lin >> 6][cc] = (rr >= 0 && rr < 64) ? plane[rr*64 + cc] : 0.f;
        }
        __syncthreads();
        float conv = fb[c];
        #pragma unroll
        for (int kh = 0; kh < 3; kh++) {
            #pragma unroll
            for (int kw = 0; kw < 3; kw++) {
                int cc = wx + kw - 1;
                float v = (cc >= 0 && cc < 64) ? tile[r + kh][cc] : 0.f;
                conv = fmaf(v, fw[c*9 + kh*3 + kw], conv);
            }
        }
        float y = fmaxf(conv, 0.f);
        acc = fmaf(y, pww[c], acc);
        __syncthreads();
    }
    atomicAdd(&slog[b*NPIX + (r0 + r)*64 + wx], acc);
}

__global__ void gate_sigmoid() {
    int i = blockIdx.x * blockDim.x + threadIdx.x;
    if (i < 2*B*NPIX) g_gate[i] = acc_sigmoid(g_gate[i]);
}

// ---------------- channel pool + SE gemm -----------------------------------
__global__ __launch_bounds__(256) void pool_kernel() {
    int t = blockIdx.z, b = blockIdx.y, c = blockIdx.x;
    const float* src  = t ? g_kn : g_qn;
    const float* gate = g_gate + t*B*NPIX + b*NPIX;
    const float* plane = src + ((size_t)(b*C + c)) * NPIX;
    float s = 0.f;
    for (int n = threadIdx.x; n < NPIX; n += 256) s = fmaf(plane[n], gate[n], s);
    __shared__ float red[8];
    for (int off = 16; off; off >>= 1) s += __shfl_down_sync(0xffffffffu, s, off);
    if ((threadIdx.x & 31) == 0) red[threadIdx.x >> 5] = s;
    __syncthreads();
    if (threadIdx.x < 8) {
        s = red[threadIdx.x];
        for (int off = 4; off; off >>= 1) s += __shfl_down_sync(0xffu, s, off);
        if (threadIdx.x == 0) g_pool[t*B*C + b*C + c] = s * (1.f / NPIX);
    }
}

__global__ __launch_bounds__(512) void chgemm(const float* __restrict__ qw,
                                              const float* __restrict__ kw) {
    int t = blockIdx.y, b = blockIdx.x;
    const float* wm = t ? kw : qw;
    __shared__ float ps[512];
    ps[threadIdx.x] = g_pool[t*B*C + b*C + threadIdx.x];
    __syncthreads();
    int o = threadIdx.x;
    float acc = 0.f;
    for (int c2 = 0; c2 < 512; c2++) acc = fmaf(ps[c2], wm[o*512 + c2], acc);
    g_cs[t*B*C + b*C + o] = acc_sigmoid(acc);
}

// ---------------- kv state + k_mean per (b, head) --------------------------
__global__ __launch_bounds__(1024) void kv_kernel(const float* __restrict__ x) {
    int h = blockIdx.x, b = blockIdx.y;
    int c0 = h * HD, jg0 = h * 16;
    __shared__ float kt[32][129];
    __shared__ float vt[32][129];
    int tid = threadIdx.x;
    int d = tid >> 5, e = tid & 31;
    const float* gate = g_gate + B*NPIX + b*NPIX;   // k side
    float acc = 0.f;
    double kmd = 0.0;
    for (int t0 = 0; t0 < NPIX; t0 += 128) {
        #pragma unroll
        for (int i = 0; i < 4; i++) {
            int lin = tid + i*1024;
            int dd = lin >> 7, col = lin & 127;
            int n = t0 + col;
            float v = g_kn[((size_t)(b*C + c0 + dd))*NPIX + n]
                      * gate[n] * g_cs[B*C + b*C + c0 + dd];
            kt[dd][col] = elu1(v);            // elu + 1
        }
        #pragma unroll
        for (int i = 0; i < 4; i++) {
            int lin = tid + i*1024;
            int col = lin >> 5, ee = lin & 31;
            vt[ee][col] = x[((size_t)(b*NPIX + t0 + col))*C + c0 + ee];
        }
        __syncthreads();
        #pragma unroll
        for (int i = 0; i < 2; i++) {
            int lin = tid + i*1024;
            int j = lin >> 7, col = lin & 127;
            float cv = g_cosT[(jg0 + j)*NPIX + t0 + col];
            float sv = g_sinT[(jg0 + j)*NPIX + t0 + col];
            float xr = kt[2*j][col], xi = kt[2*j+1][col];
            kt[2*j][col]   = cv*xr - sv*xi;
            kt[2*j+1][col] = sv*xr + cv*xi;
        }
        __syncthreads();
        float kmf = 0.f;
        #pragma unroll 8
        for (int col = 0; col < 128; col++) {
            float kd = kt[d][col];
            acc = fmaf(kd, vt[e][col], acc);
            kmf += kd;
        }
        kmd += (double)kmf;
        __syncthreads();
    }
    g_kv[((size_t)((b*HEADS + h)*HD + d))*HD + e] = acc * (1.f / NPIX);
    if (e == 0) g_km[(b*HEADS + h)*HD + d] = (float)(kmd * (1.0 / NPIX));
}

// ---------------- output: q_rope @ kv * z + lepe ---------------------------
__global__ __launch_bounds__(256) void out_kernel(const float* __restrict__ x,
        const float* __restrict__ lw, const float* __restrict__ lb,
        float* __restrict__ out) {
    int n0 = blockIdx.x * 128;
    int h = blockIdx.y, b = blockIdx.z;
    int c0 = h * HD, jg0 = h * 16;
    __shared__ float qt[32][129];
    __shared__ float kvs[32][32];
    __shared__ float kms[32];
    __shared__ float xs[4][64][32];
    int tid = threadIdx.x;
    int hh0 = n0 >> 6;
    const float* gate = g_gate + b*NPIX;  // q side
    #pragma unroll
    for (int i = 0; i < 16; i++) {
        int lin = tid + i*256;
        int dd = lin >> 7, col = lin & 127;
        int n = n0 + col;
        float v = g_qn[((size_t)(b*C + c0 + dd))*NPIX + n]
                  * gate[n] * g_cs[b*C + c0 + dd];
        qt[dd][col] = elu1(v);
    }
    #pragma unroll
    for (int i = 0; i < 32; i++) {
        int lin = tid + i*256;
        int cch  = lin & 31;
        int ccol = (lin >> 5) & 63;
        int ri   = lin >> 11;
        int rr = hh0 - 1 + ri;
        xs[ri][ccol][cch] = (rr >= 0 && rr < 64)
            ? x[((size_t)(b*NPIX + rr*64 + ccol))*C + c0 + cch] : 0.f;
    }
    #pragma unroll
    for (int i = 0; i < 4; i++) {
        int lin = tid + i*256;
        kvs[lin >> 5][lin & 31] = g_kv[((size_t)(b*HEADS + h))*HD*HD + lin];
    }
    if (tid < 32) kms[tid] = g_km[(b*HEADS + h)*HD + tid];
    __syncthreads();
    #pragma unroll
    for (int i = 0; i < 8; i++) {
        int lin = tid + i*256;
        int j = lin >> 7, col = lin & 127;
        float cv = g_cosT[(jg0 + j)*NPIX + n0 + col];
        float sv = g_sinT[(jg0 + j)*NPIX + n0 + col];
        float xr = qt[2*j][col], xi = qt[2*j+1][col];
        qt[2*j][col]   = cv*xr - sv*xi;
        qt[2*j+1][col] = sv*xr + cv*xi;
    }
    __syncthreads();

    int e = tid & 31;
    int grp = tid >> 5;
    int c = c0 + e;
    float wloc[9];
    #pragma unroll
    for (int i2 = 0; i2 < 9; i2++) wloc[i2] = lw[c*9 + i2];
    float lbv = lb[c];

    for (int ci = 0; ci < 16; ci++) {
        int col = grp*16 + ci;
        int n = n0 + col;
        float a1 = 0.f;
        float s2 = 0.f, cmp = 0.f, pe = 0.f;
        #pragma unroll
        for (int dd = 0; dd < 32; dd++) {
            float qv = qt[dd][col];
            a1 = fmaf(qv, kvs[dd][e], a1);
            float kmv = kms[dd];
            float p = qv * kmv;
            pe += fmaf(qv, kmv, -p);
            float yy = p - cmp;
            float tt = s2 + yy;
            cmp = (tt - s2) - yy;
            s2 = tt;
        }
        float a2 = s2 + pe;
        float z = 1.f / (a2 + 1e-6f);
        float att = a1 * z;
        int hh = n >> 6, ww2 = n & 63;
        int rbase = hh - hh0;
        float lep = lbv;
        #pragma unroll
        for (int kh = 0; kh < 3; kh++) {
            #pragma unroll
            for (int kw = 0; kw < 3; kw++) {
                int cc2 = ww2 + kw - 1;
                if (cc2 < 0 || cc2 >= 64) continue;
                lep = fmaf(wloc[kh*3 + kw], xs[rbase + kh][cc2][e], lep);
            }
        }
        out[((size_t)(b*NPIX + n))*C + c] = att + lep;
    }
}

// ---------------- launch ----------------------------------------------------
extern "C" void kernel_launch(void* const* d_in, const int* in_sizes, int n_in,
                              void* d_out, int out_size) {
    const float* x        = (const float*)d_in[0];
    const float* qk_w     = (const float*)d_in[1];
    const float* qk_b     = (const float*)d_in[2];
    const float* qsp_dw_w = (const float*)d_in[3];
    const float* qsp_dw_b = (const float*)d_in[4];
    const float* qsp_bn_g = (const float*)d_in[5];
    const float* qsp_bn_b = (const float*)d_in[6];
    const float* qsp_pw_w = (const float*)d_in[7];
    const float* qch_w    = (const float*)d_in[8];
    const float* ksp_dw_w = (const float*)d_in[9];
    const float* ksp_dw_b = (const float*)d_in[10];
    const float* ksp_bn_g = (const float*)d_in[11];
    const float* ksp_bn_b = (const float*)d_in[12];
    const float* ksp_pw_w = (const float*)d_in[13];
    const float* kch_w    = (const float*)d_in[14];
    const float* lepe_w   = (const float*)d_in[15];
    const float* lepe_b   = (const float*)d_in[16];
    const float* rope_cos = (const float*)d_in[17];
    const float* rope_sin = (const float*)d_in[18];
    float* out = (float*)d_out;

    repack_cos<<<4096, 256>>>(rope_cos);                               // 1
    repack_sin<<<4096, 256>>>(rope_sin);                               // 2
    setup_misc<<<130, 512>>>(qsp_dw_w, qsp_dw_b, qsp_bn_g, qsp_bn_b,
                             ksp_dw_w, ksp_dw_b, ksp_bn_g, ksp_bn_b);  // 3
    split_wk<<<1024, 256>>>(qk_w);                                     // 4
    gemm_q<<<dim3(4, 256), 256>>>(x, qk_w, qk_b);                      // 5 (profiled)
    gemm_k<<<dim3(4, 256), 256>>>(x, qk_b);                            // 6
    gate_accum<<<dim3(8, 8, B), 512>>>(0, qsp_pw_w);                   // 7
    gate_accum<<<dim3(8, 8, B), 512>>>(1, ksp_pw_w);                   // 8
    gate_sigmoid<<<(2*B*NPIX + 255)/256, 256>>>();                     // 9
    pool_kernel<<<dim3(C, B, 2), 256>>>();                             // 10
    chgemm<<<dim3(B, 2), 512>>>(qch_w, kch_w);                         // 11
    kv_kernel<<<dim3(HEADS, B), 1024>>>(x);                            // 12
    out_kernel<<<dim3(32, HEADS, B), 256>>>(x, lepe_w, lepe_b, out);   // 13
}